// round 14
// baseline (speedup 1.0000x reference)
#include <cuda_runtime.h>
#include <cuda_fp16.h>

#define N_NODES 100000
#define D_FEAT  128
#define NEG_SLOPE 0.1f

// scratch (allocation-free rule: __device__ globals)
// node_sum kept as fp16: 200KB -> fits entirely in one SM's 228KB L1, so
// kernel B's random gathers become L1 hits and stay off the LTS/atomic path.
__device__ __half g_node_sum_h[N_NODES];
__device__ float  g_r1[N_NODES];

// Kernel A: one warp per 4 nodes (measured-best shape, plain loads).
// Lane l loads float4 #l of each of the 4 rows (MLP=4). N_NODES % 4 == 0.
// Writes fp16 node sums + zeroes r1.
__global__ void node_sum_kernel(const float* __restrict__ feat) {
    int gtid = blockIdx.x * blockDim.x + threadIdx.x;
    int warp = gtid >> 5;
    int lane = gtid & 31;
    int node0 = warp * 4;
    if (node0 >= N_NODES) return;

    const float4* f4 = reinterpret_cast<const float4*>(feat);
    float4 v0 = f4[(size_t)(node0 + 0) * 32 + lane];
    float4 v1 = f4[(size_t)(node0 + 1) * 32 + lane];
    float4 v2 = f4[(size_t)(node0 + 2) * 32 + lane];
    float4 v3 = f4[(size_t)(node0 + 3) * 32 + lane];

    float s0 = (v0.x + v0.y) + (v0.z + v0.w);
    float s1 = (v1.x + v1.y) + (v1.z + v1.w);
    float s2 = (v2.x + v2.y) + (v2.z + v2.w);
    float s3 = (v3.x + v3.y) + (v3.z + v3.w);
    #pragma unroll
    for (int o = 16; o > 0; o >>= 1) {
        s0 += __shfl_xor_sync(0xFFFFFFFFu, s0, o);
        s1 += __shfl_xor_sync(0xFFFFFFFFu, s1, o);
        s2 += __shfl_xor_sync(0xFFFFFFFFu, s2, o);
        s3 += __shfl_xor_sync(0xFFFFFFFFu, s3, o);
    }
    if (lane == 0) {
        g_node_sum_h[node0 + 0] = __float2half_rn(s0);  g_r1[node0 + 0] = 0.0f;
        g_node_sum_h[node0 + 1] = __float2half_rn(s1);  g_r1[node0 + 1] = 0.0f;
        g_node_sum_h[node0 + 2] = __float2half_rn(s2);  g_r1[node0 + 2] = 0.0f;
        g_node_sum_h[node0 + 3] = __float2half_rn(s3);  g_r1[node0 + 3] = 0.0f;
    }
}

// Kernel B: 1 edge/thread (probing the measured gradient 8>4>2 edges/thread).
// Index streams use __ldcs (evict-first) so they don't evict the L1-resident
// fp16 node_sum working set; gather uses __ldg (L1-cached). REDG atomics own
// the LTS pipe.
__global__ void __launch_bounds__(256)
edge_scatter_kernel(const int* __restrict__ src,
                    const int* __restrict__ dst,
                    int n_edges) {
    int i = blockIdx.x * blockDim.x + threadIdx.x;
    if (i >= n_edges) return;
    int s = __ldcs(&src[i]);
    int d = __ldcs(&dst[i]);
    float m = __half2float(__ldg(&g_node_sum_h[s]));
    atomicAdd(&g_r1[d], m);
}

// Kernel C: leaky-relu chain + truncate-toward-zero (astype(int32) semantics),
// written as float32 (harness __output__ dtype).
__global__ void epilogue_kernel(float* __restrict__ out) {
    int i = blockIdx.x * blockDim.x + threadIdx.x;
    if (i >= N_NODES) return;
    float r1 = g_r1[i];
    float a1 = (r1 >= 0.0f) ? r1 : NEG_SLOPE * r1;
    float r2 = 16.0f * a1;                       // HIDDEN = 16
    float a2 = (r2 >= 0.0f) ? r2 : NEG_SLOPE * r2;
    float r3 = 10.0f * a2;                       // N_CLASSES = 10
    out[i] = truncf(r3);
}

extern "C" void kernel_launch(void* const* d_in, const int* in_sizes, int n_in,
                              void* d_out, int out_size) {
    const float* feat = (const float*)d_in[0];
    const int*   esrc = (const int*)d_in[1];
    const int*   edst = (const int*)d_in[2];
    int n_edges = in_sizes[1];
    float* out = (float*)d_out;

    // Kernel A: warp per 4 nodes
    {
        int threads = 256;                        // 8 warps = 32 nodes/block
        int nodes_per_block = (threads / 32) * 4;
        int blocks = (N_NODES + nodes_per_block - 1) / nodes_per_block;
        node_sum_kernel<<<blocks, threads>>>(feat);
    }
    // Kernel B: 1 edge per thread
    {
        int threads = 256;
        int blocks = (n_edges + threads - 1) / threads;
        edge_scatter_kernel<<<blocks, threads>>>(esrc, edst, n_edges);
    }
    // Kernel C
    {
        int threads = 256;
        int blocks = (N_NODES + threads - 1) / threads;
        epilogue_kernel<<<blocks, threads>>>(out);
    }
}

// round 16
// speedup vs baseline: 1.0158x; 1.0158x over previous
#include <cuda_runtime.h>
#include <cuda_fp16.h>
#include <cstdint>

#define N_NODES 100000
#define D_FEAT  128
#define NEG_SLOPE 0.1f

// scratch (allocation-free rule: __device__ globals)
// node_sum kept as fp16: 200KB -> fits in one SM's L1, so kernel B's random
// gathers become L1 hits and stay off the LTS/atomic path (measured -2us).
__device__ __half g_node_sum_h[N_NODES];
__device__ float  g_r1[N_NODES];

// ---------------------------------------------------------------------------
// Kernel A: bulk-copy pipelined row-sum.
// cp.async.bulk (UBLKCP) streams 32KB chunks (64 rows) of features into smem
// against an mbarrier (no per-warp LDG scoreboard on the fill path), double
// buffered; warps reduce the previous chunk from smem meanwhile.
// ---------------------------------------------------------------------------
#define A_BLOCKS   296                   // 2 blocks/SM
#define A_THREADS  256                   // 8 warps
#define CHUNK_ROWS 64
#define CHUNK_BYTES (CHUNK_ROWS * D_FEAT * 4)      // 32768
#define N_CHUNKS   ((N_NODES + CHUNK_ROWS - 1) / CHUNK_ROWS)  // 1563
#define A_SMEM     (2 * CHUNK_BYTES + 16)          // 2 stages + 2 mbarriers

__device__ __forceinline__ unsigned int s2u(const void* p) {
    return (unsigned int)__cvta_generic_to_shared(p);
}

__global__ void __launch_bounds__(A_THREADS, 2)
node_sum_kernel(const float* __restrict__ feat) {
    extern __shared__ __align__(16) unsigned char smem_raw[];
    float4* buf = reinterpret_cast<float4*>(smem_raw);  // 2 x 2048 float4
    unsigned long long* mbar =
        reinterpret_cast<unsigned long long*>(smem_raw + 2 * CHUNK_BYTES);

    int tid  = threadIdx.x;
    int wid  = tid >> 5;
    int lane = tid & 31;

    if (tid == 0) {
        asm volatile("mbarrier.init.shared::cta.b64 [%0], 1;" :: "r"(s2u(&mbar[0])) : "memory");
        asm volatile("mbarrier.init.shared::cta.b64 [%0], 1;" :: "r"(s2u(&mbar[1])) : "memory");
    }
    __syncthreads();

    // issue chunk for iteration `it` into stage it&1 (tid 0 only)
    auto issue = [&](int it) {
        int c = blockIdx.x + it * A_BLOCKS;
        if (c >= N_CHUNKS) return;
        int rows = N_NODES - c * CHUNK_ROWS;
        if (rows > CHUNK_ROWS) rows = CHUNK_ROWS;
        unsigned int bytes = (unsigned int)rows * (D_FEAT * 4);
        int s = it & 1;
        unsigned int mb  = s2u(&mbar[s]);
        unsigned int dst = s2u(buf + s * (CHUNK_BYTES / 16));
        const float* src = feat + (size_t)c * CHUNK_ROWS * D_FEAT;
        asm volatile("mbarrier.arrive.expect_tx.shared::cta.b64 _, [%0], %1;"
                     :: "r"(mb), "r"(bytes) : "memory");
        asm volatile("cp.async.bulk.shared::cta.global.mbarrier::complete_tx::bytes "
                     "[%0], [%1], %2, [%3];"
                     :: "r"(dst), "l"(src), "r"(bytes), "r"(mb) : "memory");
    };

    if (tid == 0) issue(0);

    for (int it = 0; blockIdx.x + it * A_BLOCKS < N_CHUNKS; it++) {
        if (tid == 0) issue(it + 1);     // other stage: consumed+synced at it-1

        int s  = it & 1;
        int ph = (it >> 1) & 1;
        unsigned int mb = s2u(&mbar[s]);
        // wait full (all threads), acquire so the smem reads below are ordered
        unsigned int done = 0;
        while (!done) {
            asm volatile(
                "{\n\t.reg .pred p;\n\t"
                "mbarrier.try_wait.parity.acquire.cta.shared::cta.b64 p, [%1], %2;\n\t"
                "selp.b32 %0, 1, 0, p;\n\t}"
                : "=r"(done) : "r"(mb), "r"(ph) : "memory");
        }

        int c = blockIdx.x + it * A_BLOCKS;
        int rows = N_NODES - c * CHUNK_ROWS;
        if (rows > CHUNK_ROWS) rows = CHUNK_ROWS;

        const float4* bs = buf + s * (CHUNK_BYTES / 16);
        int r0 = wid * 8;                // warp handles rows r0..r0+7 of chunk
        float sv[8];
        #pragma unroll
        for (int k = 0; k < 8; k++) {
            float4 v = bs[(r0 + k) * 32 + lane];     // within stage buffer
            sv[k] = (v.x + v.y) + (v.z + v.w);
        }
        #pragma unroll
        for (int o = 16; o > 0; o >>= 1) {
            #pragma unroll
            for (int k = 0; k < 8; k++)
                sv[k] += __shfl_xor_sync(0xFFFFFFFFu, sv[k], o);
        }
        if (lane == 0 && r0 < rows) {
            int node0 = c * CHUNK_ROWS + r0;         // multiple of 8
            __half h[8];
            #pragma unroll
            for (int k = 0; k < 8; k++) h[k] = __float2half_rn(sv[k]);
            *reinterpret_cast<uint4*>(&g_node_sum_h[node0]) =
                *reinterpret_cast<uint4*>(h);        // 8 halves = 16B
            float4 z = make_float4(0.f, 0.f, 0.f, 0.f);
            *reinterpret_cast<float4*>(&g_r1[node0])     = z;
            *reinterpret_cast<float4*>(&g_r1[node0 + 4]) = z;
        }
        __syncthreads();   // stage s fully consumed before reissue at it+2
    }
}

// ---------------------------------------------------------------------------
// Kernel B: 2 edges/thread (measured optimum). __ldcs index streams avoid
// evicting the L1-resident fp16 node_sum; gather via __ldg; REDG atomics own
// the LTS pipe. At its measured LSU floor (~24us).
// ---------------------------------------------------------------------------
__global__ void __launch_bounds__(256)
edge_scatter_kernel(const int* __restrict__ src,
                    const int* __restrict__ dst,
                    int n_edges2) {
    int i = blockIdx.x * blockDim.x + threadIdx.x;
    if (i >= n_edges2) return;
    const int2* src2 = reinterpret_cast<const int2*>(src);
    const int2* dst2 = reinterpret_cast<const int2*>(dst);
    int2 s = __ldcs(&src2[i]);
    int2 d = __ldcs(&dst2[i]);
    float m0 = __half2float(__ldg(&g_node_sum_h[s.x]));
    float m1 = __half2float(__ldg(&g_node_sum_h[s.y]));
    atomicAdd(&g_r1[d.x], m0);
    atomicAdd(&g_r1[d.y], m1);
}

__global__ void edge_scatter_tail_kernel(const int* __restrict__ src,
                                         const int* __restrict__ dst,
                                         int start, int n_edges) {
    int i = start + blockIdx.x * blockDim.x + threadIdx.x;
    if (i < n_edges)
        atomicAdd(&g_r1[dst[i]], __half2float(g_node_sum_h[src[i]]));
}

// Kernel C: leaky-relu chain + truncate-toward-zero (astype(int32) semantics),
// written as float32 (harness __output__ dtype).
__global__ void epilogue_kernel(float* __restrict__ out) {
    int i = blockIdx.x * blockDim.x + threadIdx.x;
    if (i >= N_NODES) return;
    float r1 = g_r1[i];
    float a1 = (r1 >= 0.0f) ? r1 : NEG_SLOPE * r1;
    float r2 = 16.0f * a1;                       // HIDDEN = 16
    float a2 = (r2 >= 0.0f) ? r2 : NEG_SLOPE * r2;
    float r3 = 10.0f * a2;                       // N_CLASSES = 10
    out[i] = truncf(r3);
}

extern "C" void kernel_launch(void* const* d_in, const int* in_sizes, int n_in,
                              void* d_out, int out_size) {
    const float* feat = (const float*)d_in[0];
    const int*   esrc = (const int*)d_in[1];
    const int*   edst = (const int*)d_in[2];
    int n_edges = in_sizes[1];
    float* out = (float*)d_out;

    // Kernel A: bulk-copy pipeline (64KB dynamic smem)
    cudaFuncSetAttribute(node_sum_kernel,
                         cudaFuncAttributeMaxDynamicSharedMemorySize, A_SMEM);
    node_sum_kernel<<<A_BLOCKS, A_THREADS, A_SMEM>>>(feat);

    // Kernel B: 2 edges per thread
    {
        int n2 = n_edges / 2;
        int threads = 256;
        int blocks = (n2 + threads - 1) / threads;
        if (blocks > 0)
            edge_scatter_kernel<<<blocks, threads>>>(esrc, edst, n2);
        int tail_start = n2 * 2;
        if (n_edges - tail_start > 0)
            edge_scatter_tail_kernel<<<1, 32>>>(esrc, edst, tail_start, n_edges);
    }
    // Kernel C
    {
        int threads = 256;
        int blocks = (N_NODES + threads - 1) / threads;
        epilogue_kernel<<<blocks, threads>>>(out);
    }
}

// round 17
// speedup vs baseline: 1.0604x; 1.0440x over previous
#include <cuda_runtime.h>
#include <cuda_fp16.h>
#include <cstdint>

#define N_NODES 100000
#define D_FEAT  128
#define NEG_SLOPE 0.1f

// scratch (allocation-free rule: __device__ globals)
// node_sum kept as fp16: 200KB -> fits in one SM's L1, so kernel B's random
// gathers become L1 hits and stay off the LTS/atomic path (measured -2us).
__device__ __half g_node_sum_h[N_NODES];
__device__ float  g_r1[N_NODES];

// ---------------------------------------------------------------------------
// Kernel A: bulk-copy pipelined row-sum (measured: ties LDG variants at the
// chip's 4.4TB/s streaming rate; keeps best-total structure).
// ---------------------------------------------------------------------------
#define A_BLOCKS   296                   // 2 blocks/SM
#define A_THREADS  256                   // 8 warps
#define CHUNK_ROWS 64
#define CHUNK_BYTES (CHUNK_ROWS * D_FEAT * 4)      // 32768
#define N_CHUNKS   ((N_NODES + CHUNK_ROWS - 1) / CHUNK_ROWS)  // 1563
#define A_SMEM     (2 * CHUNK_BYTES + 16)          // 2 stages + 2 mbarriers

__device__ __forceinline__ unsigned int s2u(const void* p) {
    return (unsigned int)__cvta_generic_to_shared(p);
}

__global__ void __launch_bounds__(A_THREADS, 2)
node_sum_kernel(const float* __restrict__ feat) {
    extern __shared__ __align__(16) unsigned char smem_raw[];
    float4* buf = reinterpret_cast<float4*>(smem_raw);  // 2 x 2048 float4
    unsigned long long* mbar =
        reinterpret_cast<unsigned long long*>(smem_raw + 2 * CHUNK_BYTES);

    int tid  = threadIdx.x;
    int wid  = tid >> 5;
    int lane = tid & 31;

    if (tid == 0) {
        asm volatile("mbarrier.init.shared::cta.b64 [%0], 1;" :: "r"(s2u(&mbar[0])) : "memory");
        asm volatile("mbarrier.init.shared::cta.b64 [%0], 1;" :: "r"(s2u(&mbar[1])) : "memory");
    }
    __syncthreads();

    auto issue = [&](int it) {
        int c = blockIdx.x + it * A_BLOCKS;
        if (c >= N_CHUNKS) return;
        int rows = N_NODES - c * CHUNK_ROWS;
        if (rows > CHUNK_ROWS) rows = CHUNK_ROWS;
        unsigned int bytes = (unsigned int)rows * (D_FEAT * 4);
        int s = it & 1;
        unsigned int mb  = s2u(&mbar[s]);
        unsigned int dst = s2u(buf + s * (CHUNK_BYTES / 16));
        const float* src = feat + (size_t)c * CHUNK_ROWS * D_FEAT;
        asm volatile("mbarrier.arrive.expect_tx.shared::cta.b64 _, [%0], %1;"
                     :: "r"(mb), "r"(bytes) : "memory");
        asm volatile("cp.async.bulk.shared::cta.global.mbarrier::complete_tx::bytes "
                     "[%0], [%1], %2, [%3];"
                     :: "r"(dst), "l"(src), "r"(bytes), "r"(mb) : "memory");
    };

    if (tid == 0) issue(0);

    for (int it = 0; blockIdx.x + it * A_BLOCKS < N_CHUNKS; it++) {
        if (tid == 0) issue(it + 1);

        int s  = it & 1;
        int ph = (it >> 1) & 1;
        unsigned int mb = s2u(&mbar[s]);
        unsigned int done = 0;
        while (!done) {
            asm volatile(
                "{\n\t.reg .pred p;\n\t"
                "mbarrier.try_wait.parity.acquire.cta.shared::cta.b64 p, [%1], %2;\n\t"
                "selp.b32 %0, 1, 0, p;\n\t}"
                : "=r"(done) : "r"(mb), "r"(ph) : "memory");
        }

        int c = blockIdx.x + it * A_BLOCKS;
        int rows = N_NODES - c * CHUNK_ROWS;
        if (rows > CHUNK_ROWS) rows = CHUNK_ROWS;

        const float4* bs = buf + s * (CHUNK_BYTES / 16);
        int r0 = wid * 8;
        float sv[8];
        #pragma unroll
        for (int k = 0; k < 8; k++) {
            float4 v = bs[(r0 + k) * 32 + lane];
            sv[k] = (v.x + v.y) + (v.z + v.w);
        }
        #pragma unroll
        for (int o = 16; o > 0; o >>= 1) {
            #pragma unroll
            for (int k = 0; k < 8; k++)
                sv[k] += __shfl_xor_sync(0xFFFFFFFFu, sv[k], o);
        }
        if (lane == 0 && r0 < rows) {
            int node0 = c * CHUNK_ROWS + r0;
            __half h[8];
            #pragma unroll
            for (int k = 0; k < 8; k++) h[k] = __float2half_rn(sv[k]);
            *reinterpret_cast<uint4*>(&g_node_sum_h[node0]) =
                *reinterpret_cast<uint4*>(h);
            float4 z = make_float4(0.f, 0.f, 0.f, 0.f);
            *reinterpret_cast<float4*>(&g_r1[node0])     = z;
            *reinterpret_cast<float4*>(&g_r1[node0 + 4]) = z;
        }
        __syncthreads();
    }
}

// ---------------------------------------------------------------------------
// Kernel B: 2 edges/thread (measured optimum), 512-thread blocks (probe).
// __ldcs index streams avoid evicting L1-resident fp16 node_sum; gather via
// __ldg; REDG atomics. At the L1TEX wavefront floor (~23.5us).
// ---------------------------------------------------------------------------
__global__ void __launch_bounds__(512)
edge_scatter_kernel(const int* __restrict__ src,
                    const int* __restrict__ dst,
                    int n_edges2, int n_edges) {
    int i = blockIdx.x * blockDim.x + threadIdx.x;
    if (i < n_edges2) {
        const int2* src2 = reinterpret_cast<const int2*>(src);
        const int2* dst2 = reinterpret_cast<const int2*>(dst);
        int2 s = __ldcs(&src2[i]);
        int2 d = __ldcs(&dst2[i]);
        float m0 = __half2float(__ldg(&g_node_sum_h[s.x]));
        float m1 = __half2float(__ldg(&g_node_sum_h[s.y]));
        atomicAdd(&g_r1[d.x], m0);
        atomicAdd(&g_r1[d.y], m1);
    }
    // odd-edge tail folded in (no extra launch)
    if (i == n_edges2 && (n_edges & 1)) {
        int e = n_edges - 1;
        atomicAdd(&g_r1[dst[e]], __half2float(g_node_sum_h[src[e]]));
    }
}

// ---------------------------------------------------------------------------
// Kernel C: leaky-relu chain + truncate-toward-zero, launched with PDL so it
// overlaps kernel B's drain; gridDepSync before touching g_r1.
// ---------------------------------------------------------------------------
__global__ void __launch_bounds__(256)
epilogue_kernel(float* __restrict__ out) {
    int i = blockIdx.x * blockDim.x + threadIdx.x;

    cudaGridDependencySynchronize();   // wait for kernel B completion + flush

    if (i >= N_NODES) return;
    float r1 = g_r1[i];
    float a1 = (r1 >= 0.0f) ? r1 : NEG_SLOPE * r1;
    float r2 = 16.0f * a1;                       // HIDDEN = 16
    float a2 = (r2 >= 0.0f) ? r2 : NEG_SLOPE * r2;
    float r3 = 10.0f * a2;                       // N_CLASSES = 10
    out[i] = truncf(r3);
}

extern "C" void kernel_launch(void* const* d_in, const int* in_sizes, int n_in,
                              void* d_out, int out_size) {
    const float* feat = (const float*)d_in[0];
    const int*   esrc = (const int*)d_in[1];
    const int*   edst = (const int*)d_in[2];
    int n_edges = in_sizes[1];
    float* out = (float*)d_out;

    // Kernel A: bulk-copy pipeline (64KB dynamic smem)
    cudaFuncSetAttribute(node_sum_kernel,
                         cudaFuncAttributeMaxDynamicSharedMemorySize, A_SMEM);
    node_sum_kernel<<<A_BLOCKS, A_THREADS, A_SMEM>>>(feat);

    // Kernel B: 2 edges per thread, 512-thread blocks
    {
        int n2 = n_edges / 2;
        int threads = 512;
        int blocks = (n2 + threads) / threads;   // +1 slot covers odd tail
        edge_scatter_kernel<<<blocks, threads>>>(esrc, edst, n2, n_edges);
    }

    // Kernel C: PDL-chained onto B
    {
        int threads = 256;
        int blocks = (N_NODES + threads - 1) / threads;
        cudaLaunchConfig_t cfg = {};
        cfg.gridDim  = dim3((unsigned)blocks, 1, 1);
        cfg.blockDim = dim3((unsigned)threads, 1, 1);
        cfg.dynamicSmemBytes = 0;
        cfg.stream = 0;
        cudaLaunchAttribute attr[1];
        attr[0].id = cudaLaunchAttributeProgrammaticStreamSerialization;
        attr[0].val.programmaticStreamSerializationAllowed = 1;
        cfg.attrs = attr;
        cfg.numAttrs = 1;
        cudaLaunchKernelEx(&cfg, epilogue_kernel, out);
    }
}